// round 1
// baseline (speedup 1.0000x reference)
#include <cuda_runtime.h>

// ProjectionSimToPointCloud: image (2048, 8192, 4) f32 -> points (2048*8192, 3) f32
//   depth = image[..., 3]
//   pitch(i) = (1 - i/h) * (FOV_UP + |FOV_DOWN|) - |FOV_DOWN|
//   yaw(j)   = j/w * 2*pi - pi
//   x = depth*cos(yaw), y = -depth*sin(yaw), z = depth*sin(pitch)

#define IMG_H 2048
#define IMG_W 8192

// Trig tables precomputed once per launch (graph-capturable, no allocation).
__device__ float g_cosYaw[IMG_W];
__device__ float g_negSinYaw[IMG_W];
__device__ float g_sinPitch[IMG_H];

__global__ void precompute_trig() {
    const int t = blockIdx.x * blockDim.x + threadIdx.x;
    const float PI_F = 3.14159265358979323846f;
    if (t < IMG_W) {
        float yaw = ((float)t / (float)IMG_W) * (2.0f * PI_F) - PI_F;
        g_cosYaw[t]    =  cosf(yaw);
        g_negSinYaw[t] = -sinf(yaw);
    }
    if (t < IMG_H) {
        // FOV_UP = 15deg, FOV_DOWN = -15deg  (radians)
        const float FOV_UP_R   = 0.2617993877991494f;   // 15/180*pi
        const float FOV_DOWN_A = 0.2617993877991494f;   // |FOV_DOWN|
        const float FOV_SPAN   = FOV_UP_R + FOV_DOWN_A; // 30deg span
        float pitch = (1.0f - (float)t / (float)IMG_H) * FOV_SPAN - FOV_DOWN_A;
        g_sinPitch[t] = sinf(pitch);
    }
}

__global__ void __launch_bounds__(256) project_kernel(
    const float4* __restrict__ img,   // (H*W) float4, .w = depth
    float* __restrict__ out)          // (H*W*3) floats
{
    const int idx = blockIdx.x * blockDim.x + threadIdx.x;   // pixel index, < H*W
    const int j = idx & (IMG_W - 1);
    const int i = idx >> 13;   // log2(IMG_W) = 13

    const float depth = img[idx].w;

    const float x = depth * g_cosYaw[j];
    const float y = depth * g_negSinYaw[j];
    const float z = depth * g_sinPitch[i];

    const int base = idx * 3;
    out[base + 0] = x;
    out[base + 1] = y;
    out[base + 2] = z;
}

extern "C" void kernel_launch(void* const* d_in, const int* in_sizes, int n_in,
                              void* d_out, int out_size) {
    const float4* img = (const float4*)d_in[0];
    float* out = (float*)d_out;

    // Fill trig tables (8192 threads covers both tables).
    precompute_trig<<<IMG_W / 256, 256>>>();

    const int n_pix = IMG_H * IMG_W;            // 16,777,216
    project_kernel<<<n_pix / 256, 256>>>(img, out);
}

// round 2
// speedup vs baseline: 1.0274x; 1.0274x over previous
#include <cuda_runtime.h>

// ProjectionSimToPointCloud: image (2048, 8192, 4) f32 -> points (2048*8192, 3) f32
//   depth = image[..., 3]
//   pitch(i) = (1 - i/h) * (FOV_UP + |FOV_DOWN|) - |FOV_DOWN|
//   yaw(j)   = j/w * 2*pi - pi
//   x = depth*cos(yaw), y = -depth*sin(yaw), z = depth*sin(pitch)

#define IMG_H 2048
#define IMG_W 8192
#define PIX_PER_THREAD 4

// Trig tables precomputed once per launch (graph-capturable, no allocation).
// 16B-aligned so the main kernel can read them as float4.
__device__ __align__(16) float g_cosYaw[IMG_W];
__device__ __align__(16) float g_negSinYaw[IMG_W];
__device__ float g_sinPitch[IMG_H];

__global__ void precompute_trig() {
    const int t = blockIdx.x * blockDim.x + threadIdx.x;
    const float PI_F = 3.14159265358979323846f;
    if (t < IMG_W) {
        float yaw = ((float)t / (float)IMG_W) * (2.0f * PI_F) - PI_F;
        g_cosYaw[t]    =  cosf(yaw);
        g_negSinYaw[t] = -sinf(yaw);
    }
    if (t < IMG_H) {
        const float FOV_UP_R   = 0.2617993877991494f;   // 15/180*pi
        const float FOV_DOWN_A = 0.2617993877991494f;   // |FOV_DOWN|
        const float FOV_SPAN   = FOV_UP_R + FOV_DOWN_A;
        float pitch = (1.0f - (float)t / (float)IMG_H) * FOV_SPAN - FOV_DOWN_A;
        g_sinPitch[t] = sinf(pitch);
    }
}

__global__ void __launch_bounds__(256) project_kernel4(
    const float* __restrict__ img,    // (H*W*4) floats, depth at 4k+3
    float* __restrict__ out)          // (H*W*3) floats
{
    const int t = blockIdx.x * blockDim.x + threadIdx.x;   // thread id
    const int p0 = t * PIX_PER_THREAD;                     // first pixel (multiple of 4)
    const int j0 = p0 & (IMG_W - 1);                       // multiple of 4, row not crossed
    const int i  = p0 >> 13;                               // log2(IMG_W) = 13

    // 4 independent depth loads, front-batched (MLP=4). Only .w (offset 12B of 16B).
    const float d0 = img[(p0 + 0) * 4 + 3];
    const float d1 = img[(p0 + 1) * 4 + 3];
    const float d2 = img[(p0 + 2) * 4 + 3];
    const float d3 = img[(p0 + 3) * 4 + 3];

    // Vector table loads (cache hits) + warp-uniform pitch.
    const float4 cy = reinterpret_cast<const float4*>(g_cosYaw)[j0 >> 2];
    const float4 sy = reinterpret_cast<const float4*>(g_negSinYaw)[j0 >> 2];
    const float  sp = g_sinPitch[i];

    // 12 output floats = 48 contiguous bytes, 16B-aligned -> 3x STG.128.
    float4 o0, o1, o2;
    o0.x = d0 * cy.x;  o0.y = d0 * sy.x;  o0.z = d0 * sp;
    o0.w = d1 * cy.y;
    o1.x = d1 * sy.y;  o1.y = d1 * sp;
    o1.z = d2 * cy.z;  o1.w = d2 * sy.z;
    o2.x = d2 * sp;
    o2.y = d3 * cy.w;  o2.z = d3 * sy.w;  o2.w = d3 * sp;

    float4* outv = reinterpret_cast<float4*>(out) + t * 3;
    outv[0] = o0;
    outv[1] = o1;
    outv[2] = o2;
}

extern "C" void kernel_launch(void* const* d_in, const int* in_sizes, int n_in,
                              void* d_out, int out_size) {
    const float* img = (const float*)d_in[0];
    float* out = (float*)d_out;

    // Fill trig tables (8192 threads covers both tables).
    precompute_trig<<<IMG_W / 256, 256>>>();

    const int n_threads = (IMG_H * IMG_W) / PIX_PER_THREAD;  // 4,194,304
    project_kernel4<<<n_threads / 256, 256>>>(img, out);
}

// round 3
// speedup vs baseline: 1.0775x; 1.0487x over previous
#include <cuda_runtime.h>

// ProjectionSimToPointCloud: image (2048, 8192, 4) f32 -> points (2048*8192, 3) f32
//   depth = image[..., 3]
//   pitch(i) = (1 - i/h) * (FOV_UP + |FOV_DOWN|) - |FOV_DOWN|
//   yaw(j)   = j/w * 2*pi - pi
//   x = depth*cos(yaw), y = -depth*sin(yaw), z = depth*sin(pitch)
//
// Single fused kernel: trig computed inline with MUFU intrinsics (~12% of MUFU
// capacity, hidden under the DRAM-bound ~71us window). No precompute launch.

#define IMG_H 2048
#define IMG_W 8192
#define PIX_PER_THREAD 4

__global__ void __launch_bounds__(256) project_fused(
    const float* __restrict__ img,    // (H*W*4) floats, depth at 4k+3
    float* __restrict__ out)          // (H*W*3) floats
{
    const int t  = blockIdx.x * blockDim.x + threadIdx.x;
    const int p0 = t * PIX_PER_THREAD;          // first pixel (multiple of 4)
    const int j0 = p0 & (IMG_W - 1);            // row not crossed (W % 4 == 0)
    const int i  = p0 >> 13;                    // log2(IMG_W) = 13

    // 4 independent depth loads, front-batched (MLP=4).
    const float d0 = img[(p0 + 0) * 4 + 3];
    const float d1 = img[(p0 + 1) * 4 + 3];
    const float d2 = img[(p0 + 2) * 4 + 3];
    const float d3 = img[(p0 + 3) * 4 + 3];

    // yaw(j) = j * (2*pi/W) - pi
    const float YAW_STEP = 7.6699039394282161e-4f;   // 2*pi/8192
    const float PI_F     = 3.14159265358979323846f;
    const float yaw0 = (float)j0 * YAW_STEP - PI_F;

    float s0, c0, s1, c1, s2, c2, s3, c3;
    __sincosf(yaw0,                  &s0, &c0);
    __sincosf(yaw0 + 1.f * YAW_STEP, &s1, &c1);
    __sincosf(yaw0 + 2.f * YAW_STEP, &s2, &c2);
    __sincosf(yaw0 + 3.f * YAW_STEP, &s3, &c3);

    // pitch(i) = FOV_UP - i * (span/H)
    const float PITCH_A = 0.26179938779914943654f;   // FOV_UP in radians
    const float PITCH_B = 2.5566346454293863e-4f;    // (30deg in rad)/2048
    const float sp = __sinf(PITCH_A - (float)i * PITCH_B);

    // 12 output floats = 48 contiguous bytes, 16B-aligned -> 3x STG.128.
    float4 o0, o1, o2;
    o0.x = d0 * c0;   o0.y = -d0 * s0;  o0.z = d0 * sp;
    o0.w = d1 * c1;
    o1.x = -d1 * s1;  o1.y = d1 * sp;
    o1.z = d2 * c2;   o1.w = -d2 * s2;
    o2.x = d2 * sp;
    o2.y = d3 * c3;   o2.z = -d3 * s3;  o2.w = d3 * sp;

    float4* outv = reinterpret_cast<float4*>(out) + t * 3;
    outv[0] = o0;
    outv[1] = o1;
    outv[2] = o2;
}

extern "C" void kernel_launch(void* const* d_in, const int* in_sizes, int n_in,
                              void* d_out, int out_size) {
    const float* img = (const float*)d_in[0];
    float* out = (float*)d_out;

    const int n_threads = (IMG_H * IMG_W) / PIX_PER_THREAD;  // 4,194,304
    project_fused<<<n_threads / 256, 256>>>(img, out);
}